// round 2
// baseline (speedup 1.0000x reference)
#include <cuda_runtime.h>
#include <cstdint>

#define N_NODES 25000
#define E_EDGES 200000
#define HID 64

// Scratch (allocation-free rule: __device__ globals)
__device__ float g_H[(long)HID * E_EDGES];     // H^T: [c][e], 51.2 MB
__device__ float g_W[(long)E_EDGES * 1024];    // per-edge w (already scaled by 1/8), 819 MB

// ---------------------------------------------------------------------------
// packed f32x2 FMA (PTX-only path; ptxas never auto-fuses)
// ---------------------------------------------------------------------------
__device__ __forceinline__ float2 ffma2(float2 a, float2 b, float2 c) {
    float2 d;
    asm("{\n\t"
        ".reg .b64 ra, rb, rc, rd;\n\t"
        "mov.b64 ra, {%2, %3};\n\t"
        "mov.b64 rb, {%4, %5};\n\t"
        "mov.b64 rc, {%6, %7};\n\t"
        "fma.rn.f32x2 rd, ra, rb, rc;\n\t"
        "mov.b64 {%0, %1}, rd;\n\t"
        "}"
        : "=f"(d.x), "=f"(d.y)
        : "f"(a.x), "f"(a.y), "f"(b.x), "f"(b.y), "f"(c.x), "f"(c.y));
    return d;
}

// ---------------------------------------------------------------------------
// K0: self-connection, writes (not adds) all N*64 outputs
// out[n, v]        = (1/4) * sum_u x[n,u]          * L0[u,v]            (v<16)
// out[n, 16+v*3+k] = (1/4) * sum_u x[n,16+u*3+k]   * L1[u,v]
// ---------------------------------------------------------------------------
__global__ void k_sc(const float* __restrict__ x,
                     const float* __restrict__ L0,
                     const float* __restrict__ L1,
                     float* __restrict__ out) {
    __shared__ float s0[256], s1[256];
    int t = threadIdx.x;
    s0[t] = L0[t];
    s1[t] = L1[t];
    __syncthreads();
    int idx = blockIdx.x * 256 + t;
    if (idx >= N_NODES * 64) return;
    int n = idx >> 6, o = idx & 63;
    const float* xr = x + (long)n * 64;
    float acc = 0.f;
    if (o < 16) {
        int v = o;
#pragma unroll
        for (int u = 0; u < 16; u++) acc += xr[u] * s0[u * 16 + v];
    } else {
        int q = o - 16;
        int v = q / 3, k = q - v * 3;
#pragma unroll
        for (int u = 0; u < 16; u++) acc += xr[16 + u * 3 + k] * s1[u * 16 + v];
    }
    out[idx] = acc * 0.25f;
}

// ---------------------------------------------------------------------------
// K1: radial basis -> hidden h (silu), stored transposed g_H[c][e]
// h = silu( radial @ W1 * (1/sqrt(8)) )
// ---------------------------------------------------------------------------
__global__ void k_h(const float* __restrict__ el, const float* __restrict__ W1) {
    __shared__ float sW1[512];
    int t = threadIdx.x;
    sW1[t] = W1[t];
    sW1[t + 256] = W1[t + 256];
    __syncthreads();
    int e = blockIdx.x * 256 + t;
    if (e >= E_EDGES) return;
    float L = el[e];
    float r[8];
#pragma unroll
    for (int i = 0; i < 8; i++) {
        float d = L - (5.0f / 7.0f) * (float)i;
        r[i] = __expf(-0.5f * d * d);
    }
#pragma unroll 8
    for (int c = 0; c < HID; c++) {
        float z = 0.f;
#pragma unroll
        for (int i = 0; i < 8; i++) z += r[i] * sW1[i * 64 + c];
        z *= 0.35355339059327373f;  // 1/sqrt(8)
        float h = z / (1.f + __expf(-z));  // silu
        g_H[(long)c * E_EDGES + e] = h;
    }
}

// ---------------------------------------------------------------------------
// K2: GEMM  w[e, j] = (1/8) * sum_c H[c,e] * W2[c, j]
// CTA tile: 128 edges x 128 cols, K=64 single pass. Thread tile 8x8 (f32x2).
// ---------------------------------------------------------------------------
__global__ void k_gemm(const float* __restrict__ W2) {
    extern __shared__ float sm[];
    float* As = sm;               // [64][128]
    float* Bs = sm + 64 * 128;    // [64][128]
    int t = threadIdx.x;
    int e0 = blockIdx.x * 128;
    int j0 = blockIdx.y * 128;

    if (e0 + 128 <= E_EDGES) {
        for (int f = t; f < 2048; f += 256) {
            int row = f >> 5, c4 = (f & 31) << 2;
            *(float4*)&As[row * 128 + c4] =
                *(const float4*)&g_H[(long)row * E_EDGES + e0 + c4];
        }
    } else {
        for (int f = t; f < 8192; f += 256) {
            int row = f >> 7, col = f & 127;
            int e = e0 + col;
            As[row * 128 + col] = (e < E_EDGES) ? g_H[(long)row * E_EDGES + e] : 0.f;
        }
    }
    for (int f = t; f < 2048; f += 256) {
        int row = f >> 5, c4 = (f & 31) << 2;
        *(float4*)&Bs[row * 128 + c4] = *(const float4*)&W2[row * 1024 + j0 + c4];
    }
    __syncthreads();

    int tx = t & 15, ty = t >> 4;
    float2 acc[8][4];
#pragma unroll
    for (int i = 0; i < 8; i++)
#pragma unroll
        for (int j = 0; j < 4; j++) acc[i][j] = make_float2(0.f, 0.f);

#pragma unroll 4
    for (int c = 0; c < 64; c++) {
        float4 a0 = *(float4*)&As[c * 128 + ty * 8];
        float4 a1 = *(float4*)&As[c * 128 + ty * 8 + 4];
        float4 b0 = *(float4*)&Bs[c * 128 + tx * 8];
        float4 b1 = *(float4*)&Bs[c * 128 + tx * 8 + 4];
        float av[8] = {a0.x, a0.y, a0.z, a0.w, a1.x, a1.y, a1.z, a1.w};
        float2 bb[4] = {make_float2(b0.x, b0.y), make_float2(b0.z, b0.w),
                        make_float2(b1.x, b1.y), make_float2(b1.z, b1.w)};
#pragma unroll
        for (int i = 0; i < 8; i++) {
            float2 aa = make_float2(av[i], av[i]);
#pragma unroll
            for (int j = 0; j < 4; j++) acc[i][j] = ffma2(aa, bb[j], acc[i][j]);
        }
    }

    const float S = 0.125f;  // 1/sqrt(64)
#pragma unroll
    for (int i = 0; i < 8; i++) {
        int e = e0 + ty * 8 + i;
        if (e < E_EDGES) {
            float4 o0 = make_float4(acc[i][0].x * S, acc[i][0].y * S,
                                    acc[i][1].x * S, acc[i][1].y * S);
            float4 o1 = make_float4(acc[i][2].x * S, acc[i][2].y * S,
                                    acc[i][3].x * S, acc[i][3].y * S);
            long base = (long)e * 1024 + j0 + tx * 8;
            *(float4*)&g_W[base] = o0;
            *(float4*)&g_W[base + 4] = o1;
        }
    }
}

// ---------------------------------------------------------------------------
// K3: per-edge epilogue. One warp per edge; 8 edges per 256-thread CTA.
// lane l: v = l&15, half = l>>4 (u-range split), shfl reduce, atomic scatter.
// ---------------------------------------------------------------------------
__global__ void k_edge(const float* __restrict__ x,
                       const float* __restrict__ ea,
                       const int* __restrict__ esrc,
                       const int* __restrict__ edst,
                       float* __restrict__ out) {
    __shared__ float s_xj0[8][16];
    __shared__ float s_b1[8][16];
    __shared__ float s_x1[8][16][3];
    __shared__ float s_sh[8][4];
    int t = threadIdx.x;
    int e0 = blockIdx.x * 8;

    if (t < 32) s_sh[t >> 2][t & 3] = ea[(long)e0 * 4 + t];
    __syncthreads();
    if (t < 128) {
        int le = t >> 4, u = t & 15;
        int src = esrc[e0 + le];
        const float* xr = x + (long)src * 64;
        float x0 = xr[u];
        float a = xr[16 + u * 3 + 0];
        float b = xr[16 + u * 3 + 1];
        float c = xr[16 + u * 3 + 2];
        s_xj0[le][u] = x0;
        s_x1[le][u][0] = a;
        s_x1[le][u][1] = b;
        s_x1[le][u][2] = c;
        // b1 includes the 1/sqrt(3) factor
        s_b1[le][u] = 0.57735026918962576f *
                      (a * s_sh[le][1] + b * s_sh[le][2] + c * s_sh[le][3]);
    }
    __syncthreads();

    int wrp = t >> 5, l = t & 31;
    int e = e0 + wrp;
    int v = l & 15, half = l >> 4;
    const float* wp = g_W + (long)e * 1024;

    float S0 = 0.f, S1 = 0.f, S2 = 0.f, S3a = 0.f, S3b = 0.f, S3c = 0.f;
#pragma unroll
    for (int i = 0; i < 8; i++) {
        int u = half * 8 + i;
        float w0 = wp[u * 16 + v];
        float w1 = wp[256 + u * 16 + v];
        float w2 = wp[512 + u * 16 + v];
        float w3 = wp[768 + u * 16 + v];
        float xj0 = s_xj0[wrp][u];
        S0 += xj0 * w0;
        S1 += s_b1[wrp][u] * w1;
        S2 += xj0 * w2;
        S3a += s_x1[wrp][u][0] * w3;
        S3b += s_x1[wrp][u][1] * w3;
        S3c += s_x1[wrp][u][2] * w3;
    }
    S0 += __shfl_xor_sync(0xFFFFFFFFu, S0, 16);
    S1 += __shfl_xor_sync(0xFFFFFFFFu, S1, 16);
    S2 += __shfl_xor_sync(0xFFFFFFFFu, S2, 16);
    S3a += __shfl_xor_sync(0xFFFFFFFFu, S3a, 16);
    S3b += __shfl_xor_sync(0xFFFFFFFFu, S3b, 16);
    S3c += __shfl_xor_sync(0xFFFFFFFFu, S3c, 16);

    if (half == 0) {
        float sh0 = s_sh[wrp][0];
        float h1 = s_sh[wrp][1], h2 = s_sh[wrp][2], h3 = s_sh[wrp][3];
        const float ALPHA = 0.17677669529663689f;  // 1/sqrt(32)
        float* o = out + (long)edst[e] * 64;
        atomicAdd(o + v, ALPHA * (sh0 * S0 + S1));
        atomicAdd(o + 16 + v * 3 + 0, ALPHA * (S2 * h1 + sh0 * S3a));
        atomicAdd(o + 16 + v * 3 + 1, ALPHA * (S2 * h2 + sh0 * S3b));
        atomicAdd(o + 16 + v * 3 + 2, ALPHA * (S2 * h3 + sh0 * S3c));
    }
}

// ---------------------------------------------------------------------------
extern "C" void kernel_launch(void* const* d_in, const int* in_sizes, int n_in,
                              void* d_out, int out_size) {
    const float* x    = (const float*)d_in[0];
    const float* ea   = (const float*)d_in[1];
    const float* el   = (const float*)d_in[2];
    const int*   esrc = (const int*)d_in[3];
    const int*   edst = (const int*)d_in[4];
    const float* W1   = (const float*)d_in[5];
    const float* W2   = (const float*)d_in[6];
    const float* L0   = (const float*)d_in[7];
    const float* L1   = (const float*)d_in[8];
    float* out = (float*)d_out;

    (void)in_sizes; (void)n_in; (void)out_size;

    // 1) self-connection initializes the full output
    k_sc<<<(N_NODES * 64 + 255) / 256, 256>>>(x, L0, L1, out);
    // 2) hidden activations
    k_h<<<(E_EDGES + 255) / 256, 256>>>(el, W1);
    // 3) big GEMM: w = h @ W2 / 8
    cudaFuncSetAttribute(k_gemm, cudaFuncAttributeMaxDynamicSharedMemorySize, 65536);
    dim3 g((E_EDGES + 127) / 128, 8);
    k_gemm<<<g, 256, 65536>>>(W2);
    // 4) per-edge contraction + scatter-add
    k_edge<<<E_EDGES / 8, 256>>>(x, ea, esrc, edst, out);
}

// round 4
// speedup vs baseline: 1.5379x; 1.5379x over previous
#include <cuda_runtime.h>
#include <cuda_bf16.h>
#include <cstdint>

#define N_NODES 25000
#define E_EDGES 200000

// Scratch (__device__ globals — allocation-free rule)
__device__ __nv_bfloat16 g_A[(size_t)E_EDGES * 192];  // [e][192]: [h_hi, h_hi, h_lo]
__device__ __nv_bfloat16 g_B[(size_t)1024 * 192];     // [n][192]: [W_hi, W_lo, W_hi]

// ---------------------------------------------------------------------------
// mma.sync m16n8k16 bf16 (row.col, fp32 accum) — plain-PTX tensor path
// ---------------------------------------------------------------------------
__device__ __forceinline__ void mma16816(float* d, const uint32_t* a, const uint32_t* b) {
    asm volatile(
        "mma.sync.aligned.m16n8k16.row.col.f32.bf16.bf16.f32 "
        "{%0,%1,%2,%3}, {%4,%5,%6,%7}, {%8,%9}, {%0,%1,%2,%3};"
        : "+f"(d[0]), "+f"(d[1]), "+f"(d[2]), "+f"(d[3])
        : "r"(a[0]), "r"(a[1]), "r"(a[2]), "r"(a[3]), "r"(b[0]), "r"(b[1]));
}

// ---------------------------------------------------------------------------
// K0: self-connection, writes (not adds) all N*64 outputs
// ---------------------------------------------------------------------------
__global__ void k_sc(const float* __restrict__ x,
                     const float* __restrict__ L0,
                     const float* __restrict__ L1,
                     float* __restrict__ out) {
    __shared__ float s0[256], s1[256];
    int t = threadIdx.x;
    s0[t] = L0[t];
    s1[t] = L1[t];
    __syncthreads();
    int idx = blockIdx.x * 256 + t;
    if (idx >= N_NODES * 64) return;
    int n = idx >> 6, o = idx & 63;
    const float* xr = x + (size_t)n * 64;
    float acc = 0.f;
    if (o < 16) {
        int v = o;
#pragma unroll
        for (int u = 0; u < 16; u++) acc += xr[u] * s0[u * 16 + v];
    } else {
        int q = o - 16;
        int v = q / 3, k = q - v * 3;
#pragma unroll
        for (int u = 0; u < 16; u++) acc += xr[16 + u * 3 + k] * s1[u * 16 + v];
    }
    out[idx] = acc * 0.25f;
}

// ---------------------------------------------------------------------------
// K1: radial -> silu hidden h (scaled by 1/8), bf16 hi/lo split -> g_A[e][192]
// ---------------------------------------------------------------------------
__global__ void k_h(const float* __restrict__ el, const float* __restrict__ W1) {
    __shared__ float sW1[512];
    int t = threadIdx.x;
    sW1[t] = W1[t];
    sW1[t + 256] = W1[t + 256];
    __syncthreads();
    int e = blockIdx.x * 256 + t;
    if (e >= E_EDGES) return;
    float L = el[e];
    float r[8];
#pragma unroll
    for (int i = 0; i < 8; i++) {
        float d = L - (5.0f / 7.0f) * (float)i;
        r[i] = __expf(-0.5f * d * d);
    }
    uint32_t hiP[32], loP[32];
#pragma unroll 4
    for (int c2 = 0; c2 < 32; c2++) {
        float z0 = 0.f, z1 = 0.f;
#pragma unroll
        for (int i = 0; i < 8; i++) {
            z0 += r[i] * sW1[i * 64 + 2 * c2];
            z1 += r[i] * sW1[i * 64 + 2 * c2 + 1];
        }
        z0 *= 0.35355339059327373f;
        z1 *= 0.35355339059327373f;
        float h0 = z0 / (1.f + __expf(-z0)) * 0.125f;  // silu * (1/8)
        float h1 = z1 / (1.f + __expf(-z1)) * 0.125f;
        __nv_bfloat16 b0 = __float2bfloat16(h0);
        __nv_bfloat16 b1 = __float2bfloat16(h1);
        __nv_bfloat16 l0 = __float2bfloat16(h0 - __bfloat162float(b0));
        __nv_bfloat16 l1 = __float2bfloat16(h1 - __bfloat162float(b1));
        hiP[c2] = ((uint32_t)__bfloat16_as_ushort(b1) << 16) | __bfloat16_as_ushort(b0);
        loP[c2] = ((uint32_t)__bfloat16_as_ushort(l1) << 16) | __bfloat16_as_ushort(l0);
    }
    uint4* row = (uint4*)(g_A + (size_t)e * 192);
    const uint4* hp = (const uint4*)hiP;
    const uint4* lp = (const uint4*)loP;
#pragma unroll
    for (int i = 0; i < 8; i++) row[i] = hp[i];
#pragma unroll
    for (int i = 0; i < 8; i++) row[8 + i] = hp[i];
#pragma unroll
    for (int i = 0; i < 8; i++) row[16 + i] = lp[i];
}

// ---------------------------------------------------------------------------
// K1b: W2 -> bf16 split, transposed to [n][192]: [hi, lo, hi]
// ---------------------------------------------------------------------------
__global__ void k_prep_B(const float* __restrict__ W2) {
    int idx = blockIdx.x * 256 + threadIdx.x;
    if (idx >= 1024 * 192) return;
    int n = idx / 192, k = idx - n * 192;
    int c = (k < 64) ? k : (k < 128 ? k - 64 : k - 128);
    float v = W2[c * 1024 + n];
    __nv_bfloat16 hi = __float2bfloat16(v);
    __nv_bfloat16 o = (k >= 64 && k < 128)
                          ? __float2bfloat16(v - __bfloat162float(hi))
                          : hi;
    g_B[(size_t)n * 192 + k] = o;
}

// ---------------------------------------------------------------------------
// K2: FUSED  GEMM (mma.sync bf16, K=192) + per-edge contraction + scatter.
// CTA = 256 threads, 128 edges. Loops 4 sections x 2 N-halves:
//   stage B half -> 128x128x192 GEMM -> w half in smem -> contract into
//   persistent per-(e,v) register accumulators. One atomic pass at the end.
// SMEM: w 128x132 f32 | A 128x200 bf16 | B 128x200 bf16 | x 128x64 f32 | ea
// ---------------------------------------------------------------------------
#define SW_PITCH 132
#define SAB_PITCH 200
#define SM_W_OFF 0
#define SM_A_OFF 67584
#define SM_B_OFF (67584 + 51200)
#define SM_X_OFF (67584 + 51200 + 51200)
#define SM_EA_OFF (67584 + 51200 + 51200 + 32768)
#define SM_TOTAL (67584 + 51200 + 51200 + 32768 + 2048)

__global__ void __launch_bounds__(256, 1)
k_fused(const float* __restrict__ x,
        const float* __restrict__ ea,
        const int* __restrict__ esrc,
        const int* __restrict__ edst,
        float* __restrict__ out) {
    extern __shared__ char smraw[];
    float* s_w = (float*)(smraw + SM_W_OFF);
    __nv_bfloat16* s_a = (__nv_bfloat16*)(smraw + SM_A_OFF);
    __nv_bfloat16* s_b = (__nv_bfloat16*)(smraw + SM_B_OFF);
    float* s_x = (float*)(smraw + SM_X_OFF);
    float* s_ea = (float*)(smraw + SM_EA_OFF);

    int tid = threadIdx.x;
    long e0 = (long)blockIdx.x * 128;

    // ---- stage A tile (zero-padded), x gather, ea ----
    for (int f = tid; f < 128 * 24; f += 256) {
        int r = f / 24, q = f - r * 24;
        uint4 val = (e0 + r < E_EDGES)
                        ? ((const uint4*)(g_A + (size_t)(e0 + r) * 192))[q]
                        : make_uint4(0u, 0u, 0u, 0u);
        *(uint4*)(s_a + r * SAB_PITCH + q * 8) = val;
    }
    for (int f = tid; f < 128 * 16; f += 256) {
        int r = f >> 4, q = f & 15;
        long e = e0 + r;
        float4 val = make_float4(0.f, 0.f, 0.f, 0.f);
        if (e < E_EDGES) val = ((const float4*)(x + (size_t)esrc[e] * 64))[q];
        ((float4*)(s_x + r * 64))[q] = val;
    }
    if (tid < 128) {
        long e = e0 + tid;
        float4 val = (e < E_EDGES) ? ((const float4*)ea)[e]
                                   : make_float4(0.f, 0.f, 0.f, 0.f);
        ((float4*)s_ea)[tid] = val;
    }

    // warp roles for GEMM
    int wid = tid >> 5, lane = tid & 31;
    int wm = (wid >> 1) * 32;
    int wn = (wid & 1) * 64;
    int grp = lane >> 2, qd = lane & 3;

    // epilogue roles + persistent accumulators
    int v = tid & 15, eg = tid >> 4;
    float o0[8], o1a[8], o1b[8], o1c[8];
#pragma unroll
    for (int i = 0; i < 8; i++) { o0[i] = 0.f; o1a[i] = 0.f; o1b[i] = 0.f; o1c[i] = 0.f; }

#pragma unroll 1
    for (int sec = 0; sec < 4; sec++) {
#pragma unroll 1
        for (int nh = 0; nh < 2; nh++) {
            int n0 = sec * 256 + nh * 128;
            // ---- stage B half: rows n0..n0+127, [n][k] ----
            for (int f = tid; f < 128 * 24; f += 256) {
                int r = f / 24, q = f - r * 24;
                uint4 val = ((const uint4*)(g_B + (size_t)(n0 + r) * 192))[q];
                *(uint4*)(s_b + r * SAB_PITCH + q * 8) = val;
            }
            __syncthreads();  // B (and first-iter A/x/ea) ready; prev w reads done

            // ---- 128x128x192 GEMM, warp tile 32x64 ----
            float acc[2][8][4];
#pragma unroll
            for (int mt = 0; mt < 2; mt++)
#pragma unroll
                for (int nt = 0; nt < 8; nt++)
#pragma unroll
                    for (int j = 0; j < 4; j++) acc[mt][nt][j] = 0.f;

            const __nv_bfloat16* aBase = s_a + (wm + grp) * SAB_PITCH + qd * 2;
            const __nv_bfloat16* bBase = s_b + (wn + grp) * SAB_PITCH + qd * 2;
#pragma unroll
            for (int kt = 0; kt < 12; kt++) {
                uint32_t af[2][4], bf[8][2];
#pragma unroll
                for (int mt = 0; mt < 2; mt++) {
                    const __nv_bfloat16* p = aBase + mt * 16 * SAB_PITCH + kt * 16;
                    af[mt][0] = *(const uint32_t*)p;
                    af[mt][1] = *(const uint32_t*)(p + 8 * SAB_PITCH);
                    af[mt][2] = *(const uint32_t*)(p + 8);
                    af[mt][3] = *(const uint32_t*)(p + 8 * SAB_PITCH + 8);
                }
#pragma unroll
                for (int nt = 0; nt < 8; nt++) {
                    const __nv_bfloat16* p = bBase + nt * 8 * SAB_PITCH + kt * 16;
                    bf[nt][0] = *(const uint32_t*)p;
                    bf[nt][1] = *(const uint32_t*)(p + 8);
                }
#pragma unroll
                for (int mt = 0; mt < 2; mt++)
#pragma unroll
                    for (int nt = 0; nt < 8; nt++)
                        mma16816(acc[mt][nt], af[mt], bf[nt]);
            }
            // store w tile (pitch 132 -> conflict-free)
#pragma unroll
            for (int mt = 0; mt < 2; mt++)
#pragma unroll
                for (int nt = 0; nt < 8; nt++) {
                    int r = wm + mt * 16 + grp;
                    int c = wn + nt * 8 + qd * 2;
                    *(float2*)&s_w[r * SW_PITCH + c] =
                        make_float2(acc[mt][nt][0], acc[mt][nt][1]);
                    *(float2*)&s_w[(r + 8) * SW_PITCH + c] =
                        make_float2(acc[mt][nt][2], acc[mt][nt][3]);
                }
            __syncthreads();  // w ready

            // ---- contract this half into persistent accumulators ----
            int ub = nh * 8;
#pragma unroll
            for (int i = 0; i < 8; i++) {
                int e = eg * 8 + i;
                const float* xr = s_x + e * 64;
                const float* wr = s_w + e * SW_PITCH + v;
                float sh0 = s_ea[e * 4 + 0];
                float h1 = s_ea[e * 4 + 1];
                float h2 = s_ea[e * 4 + 2];
                float h3 = s_ea[e * 4 + 3];
                if (sec == 0) {
                    float s = 0.f;
#pragma unroll
                    for (int u = 0; u < 8; u++) s += xr[ub + u] * wr[u * 16];
                    o0[i] += s * sh0;
                } else if (sec == 1) {
                    float s = 0.f;
#pragma unroll
                    for (int u = 0; u < 8; u++) {
                        const float* x1 = xr + 16 + (ub + u) * 3;
                        float b1 = x1[0] * h1 + x1[1] * h2 + x1[2] * h3;
                        s += b1 * wr[u * 16];
                    }
                    o0[i] += s * 0.57735026918962576f;  // 1/sqrt(3)
                } else if (sec == 2) {
                    float s = 0.f;
#pragma unroll
                    for (int u = 0; u < 8; u++) s += xr[ub + u] * wr[u * 16];
                    o1a[i] += s * h1;
                    o1b[i] += s * h2;
                    o1c[i] += s * h3;
                } else {
                    float sa = 0.f, sb2 = 0.f, sc = 0.f;
#pragma unroll
                    for (int u = 0; u < 8; u++) {
                        float wv = wr[u * 16];
                        const float* x1 = xr + 16 + (ub + u) * 3;
                        sa += x1[0] * wv;
                        sb2 += x1[1] * wv;
                        sc += x1[2] * wv;
                    }
                    o1a[i] += sh0 * sa;
                    o1b[i] += sh0 * sb2;
                    o1c[i] += sh0 * sc;
                }
            }
        }
    }

    // ---- single atomic pass ----
    const float ALPHA = 0.17677669529663689f;  // 1/sqrt(32)
#pragma unroll
    for (int i = 0; i < 8; i++) {
        long e = e0 + eg * 8 + i;
        if (e < E_EDGES) {
            float* o = out + (size_t)edst[e] * 64;
            atomicAdd(o + v, ALPHA * o0[i]);
            atomicAdd(o + 16 + v * 3 + 0, ALPHA * o1a[i]);
            atomicAdd(o + 16 + v * 3 + 1, ALPHA * o1b[i]);
            atomicAdd(o + 16 + v * 3 + 2, ALPHA * o1c[i]);
        }
    }
}

// ---------------------------------------------------------------------------
extern "C" void kernel_launch(void* const* d_in, const int* in_sizes, int n_in,
                              void* d_out, int out_size) {
    const float* x    = (const float*)d_in[0];
    const float* ea   = (const float*)d_in[1];
    const float* el   = (const float*)d_in[2];
    const int*   esrc = (const int*)d_in[3];
    const int*   edst = (const int*)d_in[4];
    const float* W1   = (const float*)d_in[5];
    const float* W2   = (const float*)d_in[6];
    const float* L0   = (const float*)d_in[7];
    const float* L1   = (const float*)d_in[8];
    float* out = (float*)d_out;

    (void)in_sizes; (void)n_in; (void)out_size;

    cudaFuncSetAttribute(k_fused, cudaFuncAttributeMaxDynamicSharedMemorySize, SM_TOTAL);

    // 1) self-connection initializes the full output
    k_sc<<<(N_NODES * 64 + 255) / 256, 256>>>(x, L0, L1, out);
    // 2) hidden activations -> bf16 split A'
    k_h<<<(E_EDGES + 255) / 256, 256>>>(el, W1);
    // 2b) W2 -> bf16 split B'
    k_prep_B<<<(1024 * 192 + 255) / 256, 256>>>(W2);
    // 3) fused GEMM + contraction + scatter
    k_fused<<<(E_EDGES + 127) / 128, 256, SM_TOTAL>>>(x, ea, esrc, edst, out);
}

// round 5
// speedup vs baseline: 2.2034x; 1.4327x over previous
#include <cuda_runtime.h>
#include <cuda_bf16.h>
#include <cstdint>

#define N_NODES 25000
#define E_EDGES 200000

// Scratch (__device__ globals — allocation-free rule)
__device__ __nv_bfloat16 g_A[(size_t)E_EDGES * 128];  // [e][128]: [h_hi | h_lo]
__device__ __nv_bfloat16 g_B[(size_t)1024 * 128];     // [n][128]: [W_hi | W_lo]

// ---------------------------------------------------------------------------
// mma.sync m16n8k16 bf16 (row.col, fp32 accum)
// ---------------------------------------------------------------------------
__device__ __forceinline__ void mma16816(float* d, const uint32_t* a, const uint32_t* b) {
    asm volatile(
        "mma.sync.aligned.m16n8k16.row.col.f32.bf16.bf16.f32 "
        "{%0,%1,%2,%3}, {%4,%5,%6,%7}, {%8,%9}, {%0,%1,%2,%3};"
        : "+f"(d[0]), "+f"(d[1]), "+f"(d[2]), "+f"(d[3])
        : "r"(a[0]), "r"(a[1]), "r"(a[2]), "r"(a[3]), "r"(b[0]), "r"(b[1]));
}
__device__ __forceinline__ uint32_t smem_u32(const void* p) {
    uint32_t a;
    asm("{ .reg .u64 t; cvta.to.shared.u64 t, %1; cvt.u32.u64 %0, t; }" : "=r"(a) : "l"(p));
    return a;
}
__device__ __forceinline__ void cpa16(uint32_t dst, const void* src, int src_sz) {
    asm volatile("cp.async.cg.shared.global [%0], [%1], 16, %2;"
                 :: "r"(dst), "l"(src), "r"(src_sz) : "memory");
}
#define CPA_COMMIT() asm volatile("cp.async.commit_group;" ::: "memory")

// ---------------------------------------------------------------------------
// K0: self-connection, writes (not adds) all N*64 outputs
// ---------------------------------------------------------------------------
__global__ void k_sc(const float* __restrict__ x,
                     const float* __restrict__ L0,
                     const float* __restrict__ L1,
                     float* __restrict__ out) {
    __shared__ float s0[256], s1[256];
    int t = threadIdx.x;
    s0[t] = L0[t];
    s1[t] = L1[t];
    __syncthreads();
    int idx = blockIdx.x * 256 + t;
    if (idx >= N_NODES * 64) return;
    int n = idx >> 6, o = idx & 63;
    const float* xr = x + (size_t)n * 64;
    float acc = 0.f;
    if (o < 16) {
        int v = o;
#pragma unroll
        for (int u = 0; u < 16; u++) acc += xr[u] * s0[u * 16 + v];
    } else {
        int q = o - 16;
        int v = q / 3, k = q - v * 3;
#pragma unroll
        for (int u = 0; u < 16; u++) acc += xr[16 + u * 3 + k] * s1[u * 16 + v];
    }
    out[idx] = acc * 0.25f;
}

// ---------------------------------------------------------------------------
// K1: radial -> silu hidden h (scaled by 1/8), bf16 hi/lo -> g_A[e][128]
// ---------------------------------------------------------------------------
__global__ void k_h(const float* __restrict__ el, const float* __restrict__ W1) {
    __shared__ float sW1[512];
    int t = threadIdx.x;
    sW1[t] = W1[t];
    sW1[t + 256] = W1[t + 256];
    __syncthreads();
    int e = blockIdx.x * 256 + t;
    if (e >= E_EDGES) return;
    float L = el[e];
    float r[8];
#pragma unroll
    for (int i = 0; i < 8; i++) {
        float d = L - (5.0f / 7.0f) * (float)i;
        r[i] = __expf(-0.5f * d * d);
    }
    uint32_t hiP[32], loP[32];
#pragma unroll 4
    for (int c2 = 0; c2 < 32; c2++) {
        float z0 = 0.f, z1 = 0.f;
#pragma unroll
        for (int i = 0; i < 8; i++) {
            z0 += r[i] * sW1[i * 64 + 2 * c2];
            z1 += r[i] * sW1[i * 64 + 2 * c2 + 1];
        }
        z0 *= 0.35355339059327373f;
        z1 *= 0.35355339059327373f;
        float h0 = z0 / (1.f + __expf(-z0)) * 0.125f;  // silu * (1/8)
        float h1 = z1 / (1.f + __expf(-z1)) * 0.125f;
        __nv_bfloat16 b0 = __float2bfloat16(h0);
        __nv_bfloat16 b1 = __float2bfloat16(h1);
        __nv_bfloat16 l0 = __float2bfloat16(h0 - __bfloat162float(b0));
        __nv_bfloat16 l1 = __float2bfloat16(h1 - __bfloat162float(b1));
        hiP[c2] = ((uint32_t)__bfloat16_as_ushort(b1) << 16) | __bfloat16_as_ushort(b0);
        loP[c2] = ((uint32_t)__bfloat16_as_ushort(l1) << 16) | __bfloat16_as_ushort(l0);
    }
    uint4* row = (uint4*)(g_A + (size_t)e * 128);
    const uint4* hp = (const uint4*)hiP;
    const uint4* lp = (const uint4*)loP;
#pragma unroll
    for (int i = 0; i < 8; i++) row[i] = hp[i];
#pragma unroll
    for (int i = 0; i < 8; i++) row[8 + i] = lp[i];
}

// ---------------------------------------------------------------------------
// K1b: W2 -> bf16 split, transposed to [n][128]: [hi | lo]
// ---------------------------------------------------------------------------
__global__ void k_prep_B(const float* __restrict__ W2) {
    int idx = blockIdx.x * 256 + threadIdx.x;
    if (idx >= 1024 * 128) return;
    int n = idx >> 7, k = idx & 127;
    int c = k & 63;
    float v = W2[c * 1024 + n];
    __nv_bfloat16 hi = __float2bfloat16(v);
    __nv_bfloat16 o = (k >= 64) ? __float2bfloat16(v - __bfloat162float(hi)) : hi;
    g_B[(size_t)n * 128 + k] = o;
}

// ---------------------------------------------------------------------------
// K2: FUSED GEMM (mma.sync bf16, K-dedup 3-term) + contraction + scatter.
// 512 threads, 128-edge tile. 8 halves (4 sections x 2 N-halves), B double-
// buffered with cp.async prefetch. Persistent per-(e,v) accumulators.
// ---------------------------------------------------------------------------
#define SAB_PITCH 136  // bf16 elements per row (conflict-free frag loads)
#define SW_PITCH 132   // f32 (conflict-free epilogue reads)
#define SM_W 0
#define SM_A 67584
#define SM_B0 102400
#define SM_B1 137216
#define SM_X 172032
#define SM_EA 204800
#define SM_TOTAL 206848

__global__ void __launch_bounds__(512, 1)
k_fused(const float* __restrict__ x,
        const float* __restrict__ ea,
        const int* __restrict__ esrc,
        const int* __restrict__ edst,
        float* __restrict__ out) {
    extern __shared__ char smraw[];
    uint32_t sbase = smem_u32(smraw);
    float* s_w = (float*)(smraw + SM_W);
    __nv_bfloat16* s_a = (__nv_bfloat16*)(smraw + SM_A);
    float* s_x = (float*)(smraw + SM_X);
    float* s_ea = (float*)(smraw + SM_EA);

    int tid = threadIdx.x;
    long e0 = (long)blockIdx.x * 128;
    int rows = (int)(E_EDGES - e0);
    if (rows > 128) rows = 128;

    // ---- initial stage: A tile, x gather, ea, B half 0 (one cp.async group)
    for (int f = tid; f < 128 * 16; f += 512) {
        int r = f >> 4, q = f & 15;
        int ok = (r < rows) ? 16 : 0;
        const char* src = (const char*)(g_A + (size_t)(e0 + (ok ? r : 0)) * 128) + q * 16;
        cpa16(sbase + SM_A + r * (SAB_PITCH * 2) + q * 16, src, ok);
    }
    for (int f = tid; f < 128 * 16; f += 512) {
        int r = f >> 4, q = f & 15;
        int ok = (r < rows) ? 16 : 0;
        int src_node = ok ? esrc[e0 + r] : 0;
        const char* src = (const char*)(x + (size_t)src_node * 64) + q * 16;
        cpa16(sbase + SM_X + r * 256 + q * 16, src, ok);
    }
    if (tid < 128) {
        int ok = (tid < rows) ? 16 : 0;
        const char* src = (const char*)(ea + (size_t)(e0 + (ok ? tid : 0)) * 4);
        cpa16(sbase + SM_EA + tid * 16, src, ok);
    }
    for (int f = tid; f < 128 * 16; f += 512) {
        int r = f >> 4, q = f & 15;
        cpa16(sbase + SM_B0 + r * (SAB_PITCH * 2) + q * 16,
              (const char*)(g_B + (size_t)r * 128) + q * 16, 16);
    }
    CPA_COMMIT();

    // warp roles (16 warps, 4x4 grid of 32x32 tiles)
    int wid = tid >> 5, lane = tid & 31;
    int wm = (wid >> 2) * 32;
    int wn = (wid & 3) * 32;
    int grp = lane >> 2, qd = lane & 3;

    // epilogue roles + persistent accumulators (4 edges per thread)
    int v = tid & 15, eg = tid >> 4;
    float o0[4], o1a[4], o1b[4], o1c[4];
#pragma unroll
    for (int i = 0; i < 4; i++) { o0[i] = 0.f; o1a[i] = 0.f; o1b[i] = 0.f; o1c[i] = 0.f; }

#pragma unroll 1
    for (int h = 0; h < 8; h++) {
        int sec = h >> 1, nh = h & 1;
        const __nv_bfloat16* s_b =
            (const __nv_bfloat16*)(smraw + ((h & 1) ? SM_B1 : SM_B0));

        // prefetch next B half into the other buffer
        if (h < 7) {
            uint32_t dstb = ((h & 1) ? SM_B0 : SM_B1) + sbase;
            const __nv_bfloat16* srcb = g_B + (size_t)(h + 1) * 128 * 128;
            for (int f = tid; f < 128 * 16; f += 512) {
                int r = f >> 4, q = f & 15;
                cpa16(dstb + r * (SAB_PITCH * 2) + q * 16,
                      (const char*)(srcb + (size_t)r * 128) + q * 16, 16);
            }
            CPA_COMMIT();
            asm volatile("cp.async.wait_group 1;" ::: "memory");
        } else {
            asm volatile("cp.async.wait_group 0;" ::: "memory");
        }
        __syncthreads();  // B(h) ready; prev epilogue done reading s_w

        // ---- 128x128x192 GEMM (3 dedup terms x 4 k-tiles), warp tile 32x32
        float acc[2][4][4];
#pragma unroll
        for (int mt = 0; mt < 2; mt++)
#pragma unroll
            for (int nt = 0; nt < 4; nt++)
#pragma unroll
                for (int j = 0; j < 4; j++) acc[mt][nt][j] = 0.f;

        const __nv_bfloat16* aBase = s_a + (wm + grp) * SAB_PITCH + qd * 2;
        const __nv_bfloat16* bBase = s_b + (wn + grp) * SAB_PITCH + qd * 2;
#pragma unroll
        for (int t = 0; t < 3; t++) {
            int ka = (t == 2) ? 64 : 0;
            int kb = (t == 1) ? 64 : 0;
#pragma unroll
            for (int kt = 0; kt < 4; kt++) {
                uint32_t af[2][4], bf[4][2];
#pragma unroll
                for (int mt = 0; mt < 2; mt++) {
                    const __nv_bfloat16* p = aBase + mt * 16 * SAB_PITCH + ka + kt * 16;
                    af[mt][0] = *(const uint32_t*)p;
                    af[mt][1] = *(const uint32_t*)(p + 8 * SAB_PITCH);
                    af[mt][2] = *(const uint32_t*)(p + 8);
                    af[mt][3] = *(const uint32_t*)(p + 8 * SAB_PITCH + 8);
                }
#pragma unroll
                for (int nt = 0; nt < 4; nt++) {
                    const __nv_bfloat16* p = bBase + nt * 8 * SAB_PITCH + kb + kt * 16;
                    bf[nt][0] = *(const uint32_t*)p;
                    bf[nt][1] = *(const uint32_t*)(p + 8);
                }
#pragma unroll
                for (int mt = 0; mt < 2; mt++)
#pragma unroll
                    for (int nt = 0; nt < 4; nt++)
                        mma16816(acc[mt][nt], af[mt], bf[nt]);
            }
        }
        // store w tile
#pragma unroll
        for (int mt = 0; mt < 2; mt++)
#pragma unroll
            for (int nt = 0; nt < 4; nt++) {
                int r = wm + mt * 16 + grp;
                int c = wn + nt * 8 + qd * 2;
                *(float2*)&s_w[r * SW_PITCH + c] =
                    make_float2(acc[mt][nt][0], acc[mt][nt][1]);
                *(float2*)&s_w[(r + 8) * SW_PITCH + c] =
                    make_float2(acc[mt][nt][2], acc[mt][nt][3]);
            }
        __syncthreads();  // w ready

        // ---- contract this half into persistent accumulators
        int ub = nh * 8;
#pragma unroll
        for (int i = 0; i < 4; i++) {
            int e = eg * 4 + i;
            const float* xr = s_x + e * 64;
            const float* wr = s_w + e * SW_PITCH + v;
            float sh0 = s_ea[e * 4 + 0];
            float h1 = s_ea[e * 4 + 1];
            float h2 = s_ea[e * 4 + 2];
            float h3 = s_ea[e * 4 + 3];
            if (sec == 0) {
                float s = 0.f;
#pragma unroll
                for (int u = 0; u < 8; u++) s += xr[ub + u] * wr[u * 16];
                o0[i] += s * sh0;
            } else if (sec == 1) {
                float s = 0.f;
#pragma unroll
                for (int u = 0; u < 8; u++) {
                    const float* x1 = xr + 16 + (ub + u) * 3;
                    float b1 = x1[0] * h1 + x1[1] * h2 + x1[2] * h3;
                    s += b1 * wr[u * 16];
                }
                o0[i] += s * 0.57735026918962576f;  // 1/sqrt(3)
            } else if (sec == 2) {
                float s = 0.f;
#pragma unroll
                for (int u = 0; u < 8; u++) s += xr[ub + u] * wr[u * 16];
                o1a[i] += s * h1;
                o1b[i] += s * h2;
                o1c[i] += s * h3;
            } else {
                float sa = 0.f, sb2 = 0.f, sc = 0.f;
#pragma unroll
                for (int u = 0; u < 8; u++) {
                    float wv = wr[u * 16];
                    const float* x1 = xr + 16 + (ub + u) * 3;
                    sa += x1[0] * wv;
                    sb2 += x1[1] * wv;
                    sc += x1[2] * wv;
                }
                o1a[i] += sh0 * sa;
                o1b[i] += sh0 * sb2;
                o1c[i] += sh0 * sc;
            }
        }
    }

    // ---- single atomic pass
    const float ALPHA = 0.17677669529663689f;  // 1/sqrt(32)
#pragma unroll
    for (int i = 0; i < 4; i++) {
        long e = e0 + eg * 4 + i;
        if (e < E_EDGES) {
            float* o = out + (size_t)edst[e] * 64;
            atomicAdd(o + v, ALPHA * o0[i]);
            atomicAdd(o + 16 + v * 3 + 0, ALPHA * o1a[i]);
            atomicAdd(o + 16 + v * 3 + 1, ALPHA * o1b[i]);
            atomicAdd(o + 16 + v * 3 + 2, ALPHA * o1c[i]);
        }
    }
}

// ---------------------------------------------------------------------------
extern "C" void kernel_launch(void* const* d_in, const int* in_sizes, int n_in,
                              void* d_out, int out_size) {
    const float* x    = (const float*)d_in[0];
    const float* ea   = (const float*)d_in[1];
    const float* el   = (const float*)d_in[2];
    const int*   esrc = (const int*)d_in[3];
    const int*   edst = (const int*)d_in[4];
    const float* W1   = (const float*)d_in[5];
    const float* W2   = (const float*)d_in[6];
    const float* L0   = (const float*)d_in[7];
    const float* L1   = (const float*)d_in[8];
    float* out = (float*)d_out;

    (void)in_sizes; (void)n_in; (void)out_size;

    cudaFuncSetAttribute(k_fused, cudaFuncAttributeMaxDynamicSharedMemorySize, SM_TOTAL);

    // 1) self-connection initializes the full output
    k_sc<<<(N_NODES * 64 + 255) / 256, 256>>>(x, L0, L1, out);
    // 2) hidden activations -> bf16 split A'
    k_h<<<(E_EDGES + 255) / 256, 256>>>(el, W1);
    // 2b) W2 -> bf16 split B'
    k_prep_B<<<(1024 * 128 + 255) / 256, 256>>>(W2);
    // 3) fused GEMM + contraction + scatter
    k_fused<<<(E_EDGES + 127) / 128, 512, SM_TOTAL>>>(x, ea, esrc, edst, out);
}

// round 6
// speedup vs baseline: 2.3005x; 1.0441x over previous
#include <cuda_runtime.h>
#include <cuda_bf16.h>
#include <cstdint>

#define N_NODES 25000
#define E_EDGES 200000

// Scratch (__device__ globals — allocation-free rule)
__device__ __nv_bfloat16 g_A[(size_t)E_EDGES * 128];  // [e][128]: [h_hi | h_lo]
__device__ __nv_bfloat16 g_B[(size_t)1024 * 128];     // [n][128]: [W_hi | W_lo]

// ---------------------------------------------------------------------------
// PTX helpers
// ---------------------------------------------------------------------------
__device__ __forceinline__ void mma16816(float* d, const uint32_t* a, const uint32_t* b) {
    asm volatile(
        "mma.sync.aligned.m16n8k16.row.col.f32.bf16.bf16.f32 "
        "{%0,%1,%2,%3}, {%4,%5,%6,%7}, {%8,%9}, {%0,%1,%2,%3};"
        : "+f"(d[0]), "+f"(d[1]), "+f"(d[2]), "+f"(d[3])
        : "r"(a[0]), "r"(a[1]), "r"(a[2]), "r"(a[3]), "r"(b[0]), "r"(b[1]));
}
__device__ __forceinline__ void ldsm_x4(uint32_t* r, uint32_t addr) {
    asm volatile("ldmatrix.sync.aligned.m8n8.x4.shared.b16 {%0,%1,%2,%3}, [%4];"
                 : "=r"(r[0]), "=r"(r[1]), "=r"(r[2]), "=r"(r[3]) : "r"(addr));
}
__device__ __forceinline__ void ldsm_x2(uint32_t* r, uint32_t addr) {
    asm volatile("ldmatrix.sync.aligned.m8n8.x2.shared.b16 {%0,%1}, [%2];"
                 : "=r"(r[0]), "=r"(r[1]) : "r"(addr));
}
__device__ __forceinline__ uint32_t smem_u32(const void* p) {
    uint32_t a;
    asm("{ .reg .u64 t; cvta.to.shared.u64 t, %1; cvt.u32.u64 %0, t; }" : "=r"(a) : "l"(p));
    return a;
}
__device__ __forceinline__ void cpa16(uint32_t dst, const void* src, int src_sz) {
    asm volatile("cp.async.cg.shared.global [%0], [%1], 16, %2;"
                 :: "r"(dst), "l"(src), "r"(src_sz) : "memory");
}
#define CPA_COMMIT() asm volatile("cp.async.commit_group;" ::: "memory")

// ---------------------------------------------------------------------------
// K_prep: merged (k_sc | k_h | k_prep_B) via blockIdx dispatch, 256 thr
//   blocks [0, 6250)        : self-connection
//   blocks [6250, 7032)     : radial->silu->bf16-split A'
//   blocks [7032, 7544)     : W2 -> bf16-split B'
// ---------------------------------------------------------------------------
#define NB_SC 6250
#define NB_H 782
#define NB_PB 512

__global__ void __launch_bounds__(256) k_prep(
    const float* __restrict__ x, const float* __restrict__ el,
    const float* __restrict__ W1, const float* __restrict__ W2,
    const float* __restrict__ L0, const float* __restrict__ L1,
    float* __restrict__ out) {
    __shared__ float sA[512];
    int b = blockIdx.x, t = threadIdx.x;
    if (b < NB_SC) {
        sA[t] = L0[t & 255];
        sA[256 + t] = L1[t & 255];
        // correct: each of first 256 threads loads both halves
        if (t < 256) { sA[t] = L0[t]; sA[256 + t] = L1[t]; }
        __syncthreads();
        int idx = b * 256 + t;
        int n = idx >> 6, o = idx & 63;
        const float* xr = x + (size_t)n * 64;
        float acc = 0.f;
        if (o < 16) {
            int v = o;
#pragma unroll
            for (int u = 0; u < 16; u++) acc += xr[u] * sA[u * 16 + v];
        } else {
            int q = o - 16;
            int v = q / 3, k = q - v * 3;
#pragma unroll
            for (int u = 0; u < 16; u++) acc += xr[16 + u * 3 + k] * sA[256 + u * 16 + v];
        }
        out[idx] = acc * 0.25f;
    } else if (b < NB_SC + NB_H) {
        sA[t] = W1[t];
        sA[t + 256] = W1[t + 256];
        __syncthreads();
        int e = (b - NB_SC) * 256 + t;
        if (e >= E_EDGES) return;
        float L = el[e];
        float r[8];
#pragma unroll
        for (int i = 0; i < 8; i++) {
            float d = L - (5.0f / 7.0f) * (float)i;
            r[i] = __expf(-0.5f * d * d);
        }
        uint32_t hiP[32], loP[32];
#pragma unroll 4
        for (int c2 = 0; c2 < 32; c2++) {
            float z0 = 0.f, z1 = 0.f;
#pragma unroll
            for (int i = 0; i < 8; i++) {
                z0 += r[i] * sA[i * 64 + 2 * c2];
                z1 += r[i] * sA[i * 64 + 2 * c2 + 1];
            }
            z0 *= 0.35355339059327373f;
            z1 *= 0.35355339059327373f;
            float h0 = z0 / (1.f + __expf(-z0)) * 0.125f;  // silu * (1/8)
            float h1 = z1 / (1.f + __expf(-z1)) * 0.125f;
            __nv_bfloat16 b0 = __float2bfloat16(h0);
            __nv_bfloat16 b1 = __float2bfloat16(h1);
            __nv_bfloat16 l0 = __float2bfloat16(h0 - __bfloat162float(b0));
            __nv_bfloat16 l1 = __float2bfloat16(h1 - __bfloat162float(b1));
            hiP[c2] = ((uint32_t)__bfloat16_as_ushort(b1) << 16) | __bfloat16_as_ushort(b0);
            loP[c2] = ((uint32_t)__bfloat16_as_ushort(l1) << 16) | __bfloat16_as_ushort(l0);
        }
        uint4* row = (uint4*)(g_A + (size_t)e * 128);
        const uint4* hp = (const uint4*)hiP;
        const uint4* lp = (const uint4*)loP;
#pragma unroll
        for (int i = 0; i < 8; i++) row[i] = hp[i];
#pragma unroll
        for (int i = 0; i < 8; i++) row[8 + i] = lp[i];
    } else {
        int idx = (b - NB_SC - NB_H) * 256 + t;
        int n = idx >> 7, k = idx & 127;
        int c = k & 63;
        float v = W2[c * 1024 + n];
        __nv_bfloat16 hi = __float2bfloat16(v);
        __nv_bfloat16 o = (k >= 64) ? __float2bfloat16(v - __bfloat162float(hi)) : hi;
        g_B[(size_t)n * 128 + k] = o;
    }
}

// ---------------------------------------------------------------------------
// K_fused: GEMM (ldmatrix + mma.sync bf16, 3-term K-dedup) + contraction +
// scatter. 512 thr, 128-edge tile, 8 halves, B double-buffered (cp.async).
// ---------------------------------------------------------------------------
#define SAB_PITCH 136  // bf16/row (ldmatrix conflict-free @272B stride)
#define SW_PITCH 132   // f32 (conflict-free epilogue reads)
#define SM_W 0
#define SM_A 67584
#define SM_B0 102400
#define SM_B1 137216
#define SM_X 172032
#define SM_EA 204800
#define SM_B1V 206848
#define SM_TOTAL 215040

__global__ void __launch_bounds__(512, 1)
k_fused(const float* __restrict__ x,
        const float* __restrict__ ea,
        const int* __restrict__ esrc,
        const int* __restrict__ edst,
        float* __restrict__ out) {
    extern __shared__ char smraw[];
    uint32_t sbase = smem_u32(smraw);
    float* s_w = (float*)(smraw + SM_W);
    float* s_x = (float*)(smraw + SM_X);
    float* s_ea = (float*)(smraw + SM_EA);
    float* s_b1 = (float*)(smraw + SM_B1V);

    int tid = threadIdx.x;
    long e0 = (long)blockIdx.x * 128;
    int rows = (int)(E_EDGES - e0);
    if (rows > 128) rows = 128;

    // ---- initial stage group 0: A tile, x gather, ea, B half 0
    for (int f = tid; f < 128 * 16; f += 512) {
        int r = f >> 4, q = f & 15;
        int ok = (r < rows) ? 16 : 0;
        const char* src = (const char*)(g_A + (size_t)(e0 + (ok ? r : 0)) * 128) + q * 16;
        cpa16(sbase + SM_A + r * (SAB_PITCH * 2) + q * 16, src, ok);
    }
    for (int f = tid; f < 128 * 16; f += 512) {
        int r = f >> 4, q = f & 15;
        int ok = (r < rows) ? 16 : 0;
        int src_node = ok ? esrc[e0 + r] : 0;
        const char* src = (const char*)(x + (size_t)src_node * 64) + q * 16;
        cpa16(sbase + SM_X + r * 256 + q * 16, src, ok);
    }
    if (tid < 128) {
        int ok = (tid < rows) ? 16 : 0;
        const char* src = (const char*)(ea + (size_t)(e0 + (ok ? tid : 0)) * 4);
        cpa16(sbase + SM_EA + tid * 16, src, ok);
    }
    for (int f = tid; f < 128 * 16; f += 512) {
        int r = f >> 4, q = f & 15;
        cpa16(sbase + SM_B0 + r * (SAB_PITCH * 2) + q * 16,
              (const char*)(g_B + (size_t)r * 128) + q * 16, 16);
    }
    CPA_COMMIT();

    // warp roles (16 warps, 4x4 grid of 32x32 tiles)
    int wid = tid >> 5, lane = tid & 31;
    int wm = (wid >> 2) * 32;
    int wn = (wid & 3) * 32;
    int grp = lane >> 2, qd = lane & 3;

    // ldmatrix lane bases (element units)
    int selA = lane >> 3;
    int rA = wm + ((selA & 1) << 3) + (lane & 7);
    int cA = (selA >> 1) << 3;
    uint32_t aF = sbase + SM_A + (uint32_t)(rA * SAB_PITCH + cA) * 2;
    int rB = wn + (lane & 7);
    int cB = ((lane >> 3) & 1) << 3;
    uint32_t bOff = (uint32_t)(rB * SAB_PITCH + cB) * 2;

    // epilogue roles + persistent accumulators (4 edges per thread)
    int v = tid & 15, eg = tid >> 4;
    float o0[4], o1a[4], o1b[4], o1c[4];
#pragma unroll
    for (int i = 0; i < 4; i++) { o0[i] = 0.f; o1a[i] = 0.f; o1b[i] = 0.f; o1c[i] = 0.f; }

#pragma unroll 1
    for (int h = 0; h < 8; h++) {
        int sec = h >> 1, nh = h & 1;
        uint32_t bufo = (h & 1) ? SM_B1 : SM_B0;

        // prefetch next B half into the other buffer
        if (h < 7) {
            uint32_t dstb = ((h & 1) ? SM_B0 : SM_B1) + sbase;
            const __nv_bfloat16* srcb = g_B + (size_t)(h + 1) * 128 * 128;
            for (int f = tid; f < 128 * 16; f += 512) {
                int r = f >> 4, q = f & 15;
                cpa16(dstb + r * (SAB_PITCH * 2) + q * 16,
                      (const char*)(srcb + (size_t)r * 128) + q * 16, 16);
            }
            CPA_COMMIT();
            asm volatile("cp.async.wait_group 1;" ::: "memory");
        } else {
            asm volatile("cp.async.wait_group 0;" ::: "memory");
        }
        __syncthreads();  // B(h) ready; prev epilogue done reading s_w

        // one-time: precompute b1[e][u] = (x1 . sh1) / sqrt(3)
        if (h == 0) {
            for (int f = tid; f < 2048; f += 512) {
                int e = f >> 4, u = f & 15;
                const float* x1 = s_x + e * 64 + 16 + u * 3;
                s_b1[f] = 0.57735026918962576f *
                          (x1[0] * s_ea[e * 4 + 1] + x1[1] * s_ea[e * 4 + 2] +
                           x1[2] * s_ea[e * 4 + 3]);
            }
        }

        // ---- 128x128x192 GEMM (3 dedup terms), ldmatrix fragments
        float acc[2][4][4];
#pragma unroll
        for (int mt = 0; mt < 2; mt++)
#pragma unroll
            for (int nt = 0; nt < 4; nt++)
#pragma unroll
                for (int j = 0; j < 4; j++) acc[mt][nt][j] = 0.f;

        uint32_t bF = sbase + bufo + bOff;

        // hi phase: A-hi x (B-hi + B-lo)
#pragma unroll
        for (int kt = 0; kt < 4; kt++) {
            int kc = kt * 16;
            uint32_t af[2][4], bh[4][2], bl[4][2];
#pragma unroll
            for (int mt = 0; mt < 2; mt++)
                ldsm_x4(af[mt], aF + (uint32_t)(mt * 16 * SAB_PITCH + kc) * 2);
#pragma unroll
            for (int nt = 0; nt < 4; nt++) {
                ldsm_x2(bh[nt], bF + (uint32_t)(nt * 8 * SAB_PITCH + kc) * 2);
                ldsm_x2(bl[nt], bF + (uint32_t)(nt * 8 * SAB_PITCH + kc + 64) * 2);
            }
#pragma unroll
            for (int mt = 0; mt < 2; mt++)
#pragma unroll
                for (int nt = 0; nt < 4; nt++) {
                    mma16816(acc[mt][nt], af[mt], bh[nt]);
                    mma16816(acc[mt][nt], af[mt], bl[nt]);
                }
        }
        // lo phase: A-lo x B-hi
#pragma unroll
        for (int kt = 0; kt < 4; kt++) {
            int kc = kt * 16;
            uint32_t af[2][4], bh[4][2];
#pragma unroll
            for (int mt = 0; mt < 2; mt++)
                ldsm_x4(af[mt], aF + (uint32_t)(mt * 16 * SAB_PITCH + kc + 64) * 2);
#pragma unroll
            for (int nt = 0; nt < 4; nt++)
                ldsm_x2(bh[nt], bF + (uint32_t)(nt * 8 * SAB_PITCH + kc) * 2);
#pragma unroll
            for (int mt = 0; mt < 2; mt++)
#pragma unroll
                for (int nt = 0; nt < 4; nt++)
                    mma16816(acc[mt][nt], af[mt], bh[nt]);
        }

        // store w tile
#pragma unroll
        for (int mt = 0; mt < 2; mt++)
#pragma unroll
            for (int nt = 0; nt < 4; nt++) {
                int r = wm + mt * 16 + grp;
                int c = wn + nt * 8 + qd * 2;
                *(float2*)&s_w[r * SW_PITCH + c] =
                    make_float2(acc[mt][nt][0], acc[mt][nt][1]);
                *(float2*)&s_w[(r + 8) * SW_PITCH + c] =
                    make_float2(acc[mt][nt][2], acc[mt][nt][3]);
            }
        __syncthreads();  // w ready (also covers s_b1 for h==0)

        // ---- contract this half into persistent accumulators
        int ub = nh * 8;
#pragma unroll
        for (int i = 0; i < 4; i++) {
            int e = eg * 4 + i;
            const float* xr = s_x + e * 64;
            const float* wr = s_w + e * SW_PITCH + v;
            if (sec == 0) {
                float s = 0.f;
#pragma unroll
                for (int u = 0; u < 8; u++) s += xr[ub + u] * wr[u * 16];
                o0[i] += s * s_ea[e * 4 + 0];
            } else if (sec == 1) {
                float s = 0.f;
#pragma unroll
                for (int u = 0; u < 8; u++) s += s_b1[e * 16 + ub + u] * wr[u * 16];
                o0[i] += s;
            } else if (sec == 2) {
                float s = 0.f;
#pragma unroll
                for (int u = 0; u < 8; u++) s += xr[ub + u] * wr[u * 16];
                o1a[i] += s * s_ea[e * 4 + 1];
                o1b[i] += s * s_ea[e * 4 + 2];
                o1c[i] += s * s_ea[e * 4 + 3];
            } else {
                float sa = 0.f, sb2 = 0.f, sc = 0.f;
#pragma unroll
                for (int u = 0; u < 8; u++) {
                    float wv = wr[u * 16];
                    const float* x1 = xr + 16 + (ub + u) * 3;
                    sa += x1[0] * wv;
                    sb2 += x1[1] * wv;
                    sc += x1[2] * wv;
                }
                float sh0 = s_ea[e * 4 + 0];
                o1a[i] += sh0 * sa;
                o1b[i] += sh0 * sb2;
                o1c[i] += sh0 * sc;
            }
        }
    }

    // ---- single atomic pass
    const float ALPHA = 0.17677669529663689f;  // 1/sqrt(32)
#pragma unroll
    for (int i = 0; i < 4; i++) {
        long e = e0 + eg * 4 + i;
        if (e < E_EDGES) {
            float* o = out + (size_t)edst[e] * 64;
            atomicAdd(o + v, ALPHA * o0[i]);
            atomicAdd(o + 16 + v * 3 + 0, ALPHA * o1a[i]);
            atomicAdd(o + 16 + v * 3 + 1, ALPHA * o1b[i]);
            atomicAdd(o + 16 + v * 3 + 2, ALPHA * o1c[i]);
        }
    }
}

// ---------------------------------------------------------------------------
extern "C" void kernel_launch(void* const* d_in, const int* in_sizes, int n_in,
                              void* d_out, int out_size) {
    const float* x    = (const float*)d_in[0];
    const float* ea   = (const float*)d_in[1];
    const float* el   = (const float*)d_in[2];
    const int*   esrc = (const int*)d_in[3];
    const int*   edst = (const int*)d_in[4];
    const float* W1   = (const float*)d_in[5];
    const float* W2   = (const float*)d_in[6];
    const float* L0   = (const float*)d_in[7];
    const float* L1   = (const float*)d_in[8];
    float* out = (float*)d_out;

    (void)in_sizes; (void)n_in; (void)out_size;

    cudaFuncSetAttribute(k_fused, cudaFuncAttributeMaxDynamicSharedMemorySize, SM_TOTAL);

    // 1) merged prep: self-connection | hidden->A' | W2->B'
    k_prep<<<NB_SC + NB_H + NB_PB, 256>>>(x, el, W1, W2, L0, L1, out);
    // 2) fused GEMM + contraction + scatter
    k_fused<<<(E_EDGES + 127) / 128, 512, SM_TOTAL>>>(x, ea, esrc, edst, out);
}